// round 7
// baseline (speedup 1.0000x reference)
#include <cuda_runtime.h>

// GlobalFilter: out = IDFT2( DFT2(x) * w ) / 196 on 14x14 grids.
// f32x2-packed (2 channels/thread), even/odd folded in all stages.
// Occupancy-focused layout: CB=32 channels/CTA (16 lane-pairs), 128 threads
// = 16 lanes x 8 work groups, smem 28672 B/CTA, regs capped for 5 CTAs/SM.

typedef unsigned long long ull;

__host__ __device__ constexpr float C14f(int t) {
    constexpr float v[14] = {
         1.0f,
         0.9009688679024191f,  0.6234898018587336f,  0.22252093395631445f,
        -0.22252093395631434f, -0.6234898018587335f, -0.9009688679024190f,
        -1.0f,
        -0.9009688679024191f, -0.6234898018587336f, -0.22252093395631445f,
         0.22252093395631434f,  0.6234898018587335f,  0.9009688679024190f
    };
    return v[t];
}
__host__ __device__ constexpr float S14f(int t) {
    constexpr float v[14] = {
         0.0f,
         0.4338837391175581f,  0.7818314824680298f,  0.9749279121818236f,
         0.9749279121818236f,  0.7818314824680299f,  0.4338837391175582f,
         0.0f,
        -0.4338837391175581f, -0.7818314824680298f, -0.9749279121818236f,
        -0.9749279121818236f, -0.7818314824680299f, -0.4338837391175582f
    };
    return v[t];
}

__device__ __forceinline__ ull f2pk(float a) {
    ull r; asm("mov.b64 %0, {%1, %1};" : "=l"(r) : "f"(a)); return r;
}
__device__ __forceinline__ ull f2pk2(float a, float b) {
    ull r; asm("mov.b64 %0, {%1, %2};" : "=l"(r) : "f"(a), "f"(b)); return r;
}
__device__ __forceinline__ ull f2fma(ull a, ull b, ull c) {
    ull r; asm("fma.rn.f32x2 %0, %1, %2, %3;" : "=l"(r) : "l"(a), "l"(b), "l"(c)); return r;
}
__device__ __forceinline__ ull f2mul(ull a, ull b) {
    ull r; asm("mul.rn.f32x2 %0, %1, %2;" : "=l"(r) : "l"(a), "l"(b)); return r;
}
__device__ __forceinline__ ull f2add(ull a, ull b) {
    ull r; asm("add.rn.f32x2 %0, %1, %2;" : "=l"(r) : "l"(a), "l"(b)); return r;
}
__device__ __forceinline__ ull f2sub(ull a, ull b) {
    ull r; asm("sub.rn.f32x2 %0, %1, %2;" : "=l"(r) : "l"(a), "l"(b)); return r;
}
__device__ __forceinline__ ull f2neg(ull a) { return a ^ 0x8000000080000000ULL; }

#define CB      32
#define LANES   16
#define NG      8
#define THREADS 128
#define SMEM_BYTES (14 * 16 * LANES * 8)

extern "C" __global__ void __launch_bounds__(THREADS, 5)
gf_kernel(const float* __restrict__ x,
          const float* __restrict__ w,
          float* __restrict__ out)
{
    extern __shared__ ull S[];   // [14][16][LANES]

    const int b    = blockIdx.x;
    const int c0   = blockIdx.y * CB;
    const int tid  = threadIdx.x;
    const int lane = tid & (LANES - 1);
    const int h    = tid >> 4;           // 0..7
    const int ch   = c0 + 2 * lane;

    // ---------------- load x[b, :, ch..ch+1] ----------------
    const float* xb = x + (size_t)b * 196 * 384 + ch;
    #pragma unroll 5
    for (int n = h; n < 196; n += NG) {
        S[((n / 14) * 16 + (n % 14)) * LANES + lane] = *(const ull*)(xb + (size_t)n * 384);
    }
    __syncthreads();

    // ---------------- stage 1: real DFT along rows (a2 -> k2), folded ----------------
    for (int a1 = h; a1 < 14; a1 += NG) {
        ull r[14];
        #pragma unroll
        for (int j = 0; j < 14; ++j) r[j] = S[(a1 * 16 + j) * LANES + lane];

        const ull p = f2add(r[0], r[7]);
        const ull m = f2sub(r[0], r[7]);
        ull e[7], o[7];
        #pragma unroll
        for (int j = 1; j < 7; ++j) { e[j] = f2add(r[j], r[14 - j]); o[j] = f2sub(r[j], r[14 - j]); }

        // k = 0
        {
            ull sr = p;
            #pragma unroll
            for (int j = 1; j < 7; ++j) sr = f2add(sr, e[j]);
            S[(a1 * 16 + 0) * LANES + lane] = sr;
            S[(a1 * 16 + 8) * LANES + lane] = 0ULL;
        }
        // k = 7
        {
            ull sr = m;
            #pragma unroll
            for (int j = 1; j < 7; ++j) sr = (j & 1) ? f2sub(sr, e[j]) : f2add(sr, e[j]);
            S[(a1 * 16 + 7)  * LANES + lane] = sr;
            S[(a1 * 16 + 15) * LANES + lane] = 0ULL;
        }
        // k = 1..6
        #pragma unroll
        for (int k = 1; k < 7; ++k) {
            ull sr = (k & 1) ? m : p;
            ull si;
            #pragma unroll
            for (int j = 1; j < 7; ++j) {
                const int t = (j * k) % 14;
                sr = f2fma(e[j], f2pk(C14f(t)), sr);
                if (j == 1) si = f2mul(o[1], f2pk(-S14f(t)));
                else        si = f2fma(o[j], f2pk(-S14f(t)), si);
            }
            S[(a1 * 16 + k)     * LANES + lane] = sr;
            S[(a1 * 16 + 8 + k) * LANES + lane] = si;
        }
    }
    __syncthreads();

    // ------- middle: column k2 = h. phase A: fwd DFT + weight -> Z; phase B: inv DFT -------
    {
        const int k2 = h;
        // ---- phase A ----
        {
            ull yr[14], yi[14];
            #pragma unroll
            for (int j = 0; j < 14; ++j) {
                yr[j] = S[(j * 16 + k2)     * LANES + lane];
                yi[j] = S[(j * 16 + 8 + k2) * LANES + lane];
            }
            const ull pr = f2add(yr[0], yr[7]), mr = f2sub(yr[0], yr[7]);
            const ull pi = f2add(yi[0], yi[7]), mi = f2sub(yi[0], yi[7]);
            ull Er[7], Ei[7], Or[7], Oi[7];
            #pragma unroll
            for (int j = 1; j < 7; ++j) {
                Er[j] = f2add(yr[j], yr[14 - j]); Or[j] = f2sub(yr[j], yr[14 - j]);
                Ei[j] = f2add(yi[j], yi[14 - j]); Oi[j] = f2sub(yi[j], yi[14 - j]);
            }

            auto wmul_store = [&](int k1, ull Xr, ull Xi) {
                const float4 w4 = *(const float4*)(w + ((size_t)(k1 * 8 + k2) * 384 + ch) * 2);
                const ull wr = f2pk2(w4.x, w4.z);
                const ull wi = f2pk2(w4.y, w4.w);
                const ull Zr = f2fma(Xi, f2neg(wi), f2mul(Xr, wr));
                const ull Zi = f2fma(Xi, wr,        f2mul(Xr, wi));
                S[(k1 * 16 + k2)     * LANES + lane] = Zr;
                S[(k1 * 16 + 8 + k2) * LANES + lane] = Zi;
            };

            // k1 = 0
            {
                ull Xr = pr, Xi = pi;
                #pragma unroll
                for (int j = 1; j < 7; ++j) { Xr = f2add(Xr, Er[j]); Xi = f2add(Xi, Ei[j]); }
                wmul_store(0, Xr, Xi);
            }
            // k1 = 7
            {
                ull Xr = mr, Xi = mi;
                #pragma unroll
                for (int j = 1; j < 7; ++j) {
                    if (j & 1) { Xr = f2sub(Xr, Er[j]); Xi = f2sub(Xi, Ei[j]); }
                    else       { Xr = f2add(Xr, Er[j]); Xi = f2add(Xi, Ei[j]); }
                }
                wmul_store(7, Xr, Xi);
            }
            // pairs k1 / 14-k1
            #pragma unroll
            for (int k1 = 1; k1 < 7; ++k1) {
                ull Ar = (k1 & 1) ? mr : pr;
                ull Ai = (k1 & 1) ? mi : pi;
                ull Br, Bi;
                #pragma unroll
                for (int j = 1; j < 7; ++j) {
                    const int t = (j * k1) % 14;
                    Ar = f2fma(Er[j], f2pk(C14f(t)), Ar);
                    Ai = f2fma(Ei[j], f2pk(C14f(t)), Ai);
                    if (j == 1) { Br = f2mul(Or[1], f2pk(S14f(t))); Bi = f2mul(Oi[1], f2pk(S14f(t))); }
                    else        { Br = f2fma(Or[j], f2pk(S14f(t)), Br); Bi = f2fma(Oi[j], f2pk(S14f(t)), Bi); }
                }
                wmul_store(k1,      f2add(Ar, Bi), f2sub(Ai, Br));
                wmul_store(14 - k1, f2sub(Ar, Bi), f2add(Ai, Br));
            }
        }
        // ---- phase B ----
        {
            ull Zr[14], Zi[14];
            #pragma unroll
            for (int k = 0; k < 14; ++k) {
                Zr[k] = S[(k * 16 + k2)     * LANES + lane];
                Zi[k] = S[(k * 16 + 8 + k2) * LANES + lane];
            }
            const ull pr = f2add(Zr[0], Zr[7]), mr = f2sub(Zr[0], Zr[7]);
            const ull pi = f2add(Zi[0], Zi[7]), mi = f2sub(Zi[0], Zi[7]);
            ull Er[7], Ei[7], Or[7], Oi[7];
            #pragma unroll
            for (int k = 1; k < 7; ++k) {
                Er[k] = f2add(Zr[k], Zr[14 - k]); Or[k] = f2sub(Zr[k], Zr[14 - k]);
                Ei[k] = f2add(Zi[k], Zi[14 - k]); Oi[k] = f2sub(Zi[k], Zi[14 - k]);
            }

            // a1 = 0
            {
                ull zr = pr, zi = pi;
                #pragma unroll
                for (int k = 1; k < 7; ++k) { zr = f2add(zr, Er[k]); zi = f2add(zi, Ei[k]); }
                S[(0 * 16 + k2)     * LANES + lane] = zr;
                S[(0 * 16 + 8 + k2) * LANES + lane] = zi;
            }
            // a1 = 7
            {
                ull zr = mr, zi = mi;
                #pragma unroll
                for (int k = 1; k < 7; ++k) {
                    if (k & 1) { zr = f2sub(zr, Er[k]); zi = f2sub(zi, Ei[k]); }
                    else       { zr = f2add(zr, Er[k]); zi = f2add(zi, Ei[k]); }
                }
                S[(7 * 16 + k2)     * LANES + lane] = zr;
                S[(7 * 16 + 8 + k2) * LANES + lane] = zi;
            }
            // pairs a1 / 14-a1
            #pragma unroll
            for (int a1 = 1; a1 < 7; ++a1) {
                ull Ar = (a1 & 1) ? mr : pr;
                ull Ai = (a1 & 1) ? mi : pi;
                ull Br, Bi;
                #pragma unroll
                for (int k = 1; k < 7; ++k) {
                    const int t = (k * a1) % 14;
                    Ar = f2fma(Er[k], f2pk(C14f(t)), Ar);
                    Ai = f2fma(Ei[k], f2pk(C14f(t)), Ai);
                    if (k == 1) { Br = f2mul(Or[1], f2pk(S14f(t))); Bi = f2mul(Oi[1], f2pk(S14f(t))); }
                    else        { Br = f2fma(Or[k], f2pk(S14f(t)), Br); Bi = f2fma(Oi[k], f2pk(S14f(t)), Bi); }
                }
                S[(a1 * 16 + k2)            * LANES + lane] = f2sub(Ar, Bi);
                S[(a1 * 16 + 8 + k2)        * LANES + lane] = f2add(Ai, Br);
                S[((14 - a1) * 16 + k2)     * LANES + lane] = f2add(Ar, Bi);
                S[((14 - a1) * 16 + 8 + k2) * LANES + lane] = f2sub(Ai, Br);
            }
        }
    }
    __syncthreads();

    // ---------------- stage 5: irfft along rows (k2 -> a2), folded, store ----------------
    float* ob = out + (size_t)b * 196 * 384 + ch;
    for (int a1 = h; a1 < 14; a1 += NG) {
        ull zr[8], zi[8];
        #pragma unroll
        for (int k = 0; k < 8; ++k) {
            zr[k] = S[(a1 * 16 + k)     * LANES + lane];
            zi[k] = S[(a1 * 16 + 8 + k) * LANES + lane];
        }
        const ull s1 = f2pk(1.0f / 196.0f);
        const ull s2 = f2pk(2.0f / 196.0f);
        zr[0] = f2mul(zr[0], s1);
        zr[7] = f2mul(zr[7], s1);
        #pragma unroll
        for (int k = 1; k < 7; ++k) { zr[k] = f2mul(zr[k], s2); zi[k] = f2mul(zi[k], s2); }

        const ull p = f2add(zr[0], zr[7]);
        const ull m = f2sub(zr[0], zr[7]);

        // a2 = 0
        {
            ull v = p;
            #pragma unroll
            for (int k = 1; k < 7; ++k) v = f2add(v, zr[k]);
            *(ull*)(ob + (size_t)(a1 * 14 + 0) * 384) = v;
        }
        // a2 = 7
        {
            ull v = m;
            #pragma unroll
            for (int k = 1; k < 7; ++k) v = (k & 1) ? f2sub(v, zr[k]) : f2add(v, zr[k]);
            *(ull*)(ob + (size_t)(a1 * 14 + 7) * 384) = v;
        }
        // pairs a2 / 14-a2
        #pragma unroll
        for (int a2 = 1; a2 < 7; ++a2) {
            ull E = (a2 & 1) ? m : p;
            ull Od;
            #pragma unroll
            for (int k = 1; k < 7; ++k) {
                const int t = (k * a2) % 14;
                E = f2fma(zr[k], f2pk(C14f(t)), E);
                if (k == 1) Od = f2mul(zi[1], f2pk(-S14f(t)));
                else        Od = f2fma(zi[k], f2pk(-S14f(t)), Od);
            }
            *(ull*)(ob + (size_t)(a1 * 14 + a2)        * 384) = f2add(E, Od);
            *(ull*)(ob + (size_t)(a1 * 14 + (14 - a2)) * 384) = f2sub(E, Od);
        }
    }
}

extern "C" void kernel_launch(void* const* d_in, const int* in_sizes, int n_in,
                              void* d_out, int out_size)
{
    const float* x = (const float*)d_in[0];   // [512,196,384] f32
    const float* w = (const float*)d_in[1];   // [14,8,384,2]  f32
    float* out = (float*)d_out;               // [512,196,384] f32

    cudaFuncSetAttribute(gf_kernel, cudaFuncAttributeMaxDynamicSharedMemorySize, SMEM_BYTES);

    dim3 grid(512, 384 / CB);
    gf_kernel<<<grid, THREADS, SMEM_BYTES>>>(x, w, out);
}

// round 9
// speedup vs baseline: 1.3033x; 1.3033x over previous
#include <cuda_runtime.h>

// GlobalFilter: out = IDFT2( DFT2(x) * w ) / 196 on 14x14 grids.
// f32x2-packed (2 channels/thread), even/odd folded everywhere.
// smem-instruction-minimized: stage1 reads gmem directly into registers
// (no spatial smem pass), all spectral smem traffic is 128-bit (re,im) pairs,
// middle stage fully fused in registers.
//
// CTA = (batch, 64-ch block). 128 threads = 32 lane-pairs x 4 groups (h).
// smem S2[a1(14)][k(8)][lane(32)] of ulonglong2: 57344 B -> 3 CTAs/SM.

typedef unsigned long long ull;

__host__ __device__ constexpr float C14f(int t) {
    constexpr float v[14] = {
         1.0f,
         0.9009688679024191f,  0.6234898018587336f,  0.22252093395631445f,
        -0.22252093395631434f, -0.6234898018587335f, -0.9009688679024190f,
        -1.0f,
        -0.9009688679024191f, -0.6234898018587336f, -0.22252093395631445f,
         0.22252093395631434f,  0.6234898018587335f,  0.9009688679024190f
    };
    return v[t];
}
__host__ __device__ constexpr float S14f(int t) {
    constexpr float v[14] = {
         0.0f,
         0.4338837391175581f,  0.7818314824680298f,  0.9749279121818236f,
         0.9749279121818236f,  0.7818314824680299f,  0.4338837391175582f,
         0.0f,
        -0.4338837391175581f, -0.7818314824680298f, -0.9749279121818236f,
        -0.9749279121818236f, -0.7818314824680299f, -0.4338837391175582f
    };
    return v[t];
}

__device__ __forceinline__ ull f2pk(float a) {
    ull r; asm("mov.b64 %0, {%1, %1};" : "=l"(r) : "f"(a)); return r;
}
__device__ __forceinline__ ull f2pk2(float a, float b) {
    ull r; asm("mov.b64 %0, {%1, %2};" : "=l"(r) : "f"(a), "f"(b)); return r;
}
__device__ __forceinline__ ull f2fma(ull a, ull b, ull c) {
    ull r; asm("fma.rn.f32x2 %0, %1, %2, %3;" : "=l"(r) : "l"(a), "l"(b), "l"(c)); return r;
}
__device__ __forceinline__ ull f2mul(ull a, ull b) {
    ull r; asm("mul.rn.f32x2 %0, %1, %2;" : "=l"(r) : "l"(a), "l"(b)); return r;
}
__device__ __forceinline__ ull f2add(ull a, ull b) {
    ull r; asm("add.rn.f32x2 %0, %1, %2;" : "=l"(r) : "l"(a), "l"(b)); return r;
}
__device__ __forceinline__ ull f2sub(ull a, ull b) {
    ull r; asm("sub.rn.f32x2 %0, %1, %2;" : "=l"(r) : "l"(a), "l"(b)); return r;
}
__device__ __forceinline__ ull f2neg(ull a) { return a ^ 0x8000000080000000ULL; }

// acc += v * C14f(t), exploiting C = +/-1
__device__ __forceinline__ ull f2accC(ull acc, ull v, int t) {
    if (C14f(t) ==  1.0f) return f2add(acc, v);
    if (C14f(t) == -1.0f) return f2sub(acc, v);
    return f2fma(v, f2pk(C14f(t)), acc);
}

#define CB      64
#define LANES   32
#define THREADS 128
#define SMEM_BYTES (14 * 8 * LANES * 16)

extern "C" __global__ void __launch_bounds__(THREADS, 3)
gf_kernel(const float* __restrict__ x,
          const float* __restrict__ w,
          float* __restrict__ out)
{
    extern __shared__ ulonglong2 S2[];   // [14][8][LANES] (re, im)

    const int b    = blockIdx.x;
    const int c0   = blockIdx.y * CB;
    const int tid  = threadIdx.x;
    const int lane = tid & (LANES - 1);
    const int h    = tid >> 5;           // 0..3
    const int ch   = c0 + 2 * lane;

    // ------- stage 1: gmem -> registers -> folded rfft -> spectral smem -------
    const float* xb = x + (size_t)b * 196 * 384 + ch;
    for (int a1 = h; a1 < 14; a1 += 4) {
        const float* xr = xb + (size_t)a1 * 14 * 384;
        ull r[14];
        #pragma unroll
        for (int j = 0; j < 14; ++j) r[j] = *(const ull*)(xr + (size_t)j * 384);

        const ull p = f2add(r[0], r[7]);
        const ull m = f2sub(r[0], r[7]);
        ull e[7], o[7];
        #pragma unroll
        for (int j = 1; j < 7; ++j) { e[j] = f2add(r[j], r[14 - j]); o[j] = f2sub(r[j], r[14 - j]); }

        ulonglong2* srow = S2 + a1 * 8 * LANES + lane;
        // k = 0
        {
            ull sr = p;
            #pragma unroll
            for (int j = 1; j < 7; ++j) sr = f2add(sr, e[j]);
            srow[0 * LANES] = make_ulonglong2(sr, 0ULL);
        }
        // k = 7
        {
            ull sr = m;
            #pragma unroll
            for (int j = 1; j < 7; ++j) sr = (j & 1) ? f2sub(sr, e[j]) : f2add(sr, e[j]);
            srow[7 * LANES] = make_ulonglong2(sr, 0ULL);
        }
        // k = 1..6
        #pragma unroll
        for (int k = 1; k < 7; ++k) {
            ull sr = (k & 1) ? m : p;
            ull si;
            #pragma unroll
            for (int j = 1; j < 7; ++j) {
                const int t = (j * k) % 14;
                sr = f2fma(e[j], f2pk(C14f(t)), sr);
                if (j == 1) si = f2mul(o[1], f2pk(-S14f(t)));
                else        si = f2fma(o[j], f2pk(-S14f(t)), si);
            }
            srow[k * LANES] = make_ulonglong2(sr, si);
        }
    }
    __syncthreads();

    // ------- middle (FUSED): per-column fwd DFT -> *w -> inverse DFT, in regs -------
    for (int k2 = 2 * h; k2 < 2 * h + 2; ++k2) {
        ulonglong2* scol = S2 + k2 * LANES + lane;   // + j*8*LANES per row

        ull pr, mr, pi, mi, Er[7], Ei[7], Or[7], Oi[7];
        {
            ull yr[14], yi[14];
            #pragma unroll
            for (int j = 0; j < 14; ++j) {
                const ulonglong2 v = scol[j * 8 * LANES];
                yr[j] = v.x; yi[j] = v.y;
            }
            pr = f2add(yr[0], yr[7]); mr = f2sub(yr[0], yr[7]);
            pi = f2add(yi[0], yi[7]); mi = f2sub(yi[0], yi[7]);
            #pragma unroll
            for (int j = 1; j < 7; ++j) {
                Er[j] = f2add(yr[j], yr[14 - j]); Or[j] = f2sub(yr[j], yr[14 - j]);
                Ei[j] = f2add(yi[j], yi[14 - j]); Oi[j] = f2sub(yi[j], yi[14 - j]);
            }
        }

        const float* wcol = w + ((size_t)k2 * 384 + ch) * 2;   // + k1*8*384*2 per row

        ull CPr[8], CPi[8], SQr[7], SQi[7];
        // k1 = 0 and k1 = 7 -> init CP accumulators
        {
            ull X0r = pr, X0i = pi, X7r = mr, X7i = mi;
            #pragma unroll
            for (int j = 1; j < 7; ++j) {
                X0r = f2add(X0r, Er[j]); X0i = f2add(X0i, Ei[j]);
                if (j & 1) { X7r = f2sub(X7r, Er[j]); X7i = f2sub(X7i, Ei[j]); }
                else       { X7r = f2add(X7r, Er[j]); X7i = f2add(X7i, Ei[j]); }
            }
            const float4 w0 = *(const float4*)(wcol + (size_t)0 * 8 * 384 * 2);
            const float4 w7 = *(const float4*)(wcol + (size_t)7 * 8 * 384 * 2);
            const ull w0r = f2pk2(w0.x, w0.z), w0i = f2pk2(w0.y, w0.w);
            const ull w7r = f2pk2(w7.x, w7.z), w7i = f2pk2(w7.y, w7.w);
            const ull Z0r = f2fma(X0i, f2neg(w0i), f2mul(X0r, w0r));
            const ull Z0i = f2fma(X0i, w0r,        f2mul(X0r, w0i));
            const ull Z7r = f2fma(X7i, f2neg(w7i), f2mul(X7r, w7r));
            const ull Z7i = f2fma(X7i, w7r,        f2mul(X7r, w7i));
            const ull epr = f2add(Z0r, Z7r), emr = f2sub(Z0r, Z7r);
            const ull epi = f2add(Z0i, Z7i), emi = f2sub(Z0i, Z7i);
            #pragma unroll
            for (int a1 = 0; a1 < 8; ++a1) {
                CPr[a1] = (a1 & 1) ? emr : epr;
                CPi[a1] = (a1 & 1) ? emi : epi;
            }
        }

        // k1 pairs (k1, 14-k1), k1 = 1..6
        #pragma unroll
        for (int k1 = 1; k1 < 7; ++k1) {
            ull Ar = (k1 & 1) ? mr : pr;
            ull Ai = (k1 & 1) ? mi : pi;
            ull Br, Bi;
            #pragma unroll
            for (int j = 1; j < 7; ++j) {
                const int t = (j * k1) % 14;
                Ar = f2fma(Er[j], f2pk(C14f(t)), Ar);
                Ai = f2fma(Ei[j], f2pk(C14f(t)), Ai);
                if (j == 1) { Br = f2mul(Or[1], f2pk(S14f(t))); Bi = f2mul(Oi[1], f2pk(S14f(t))); }
                else        { Br = f2fma(Or[j], f2pk(S14f(t)), Br); Bi = f2fma(Oi[j], f2pk(S14f(t)), Bi); }
            }
            // X[k1] = A - iB, X[14-k1] = A + iB
            const ull X1r = f2add(Ar, Bi), X1i = f2sub(Ai, Br);
            const ull X2r = f2sub(Ar, Bi), X2i = f2add(Ai, Br);
            const float4 wa = *(const float4*)(wcol + (size_t)k1        * 8 * 384 * 2);
            const float4 wb = *(const float4*)(wcol + (size_t)(14 - k1) * 8 * 384 * 2);
            const ull war = f2pk2(wa.x, wa.z), wai = f2pk2(wa.y, wa.w);
            const ull wbr = f2pk2(wb.x, wb.z), wbi = f2pk2(wb.y, wb.w);
            const ull Z1r = f2fma(X1i, f2neg(wai), f2mul(X1r, war));
            const ull Z1i = f2fma(X1i, war,        f2mul(X1r, wai));
            const ull Z2r = f2fma(X2i, f2neg(wbi), f2mul(X2r, wbr));
            const ull Z2i = f2fma(X2i, wbr,        f2mul(X2r, wbi));
            // fold Z pair for the inverse transform
            const ull Ezr = f2add(Z1r, Z2r), Ezi = f2add(Z1i, Z2i);
            const ull Ozr = f2sub(Z1r, Z2r), Ozi = f2sub(Z1i, Z2i);
            #pragma unroll
            for (int a1 = 0; a1 < 8; ++a1) {
                const int t = (k1 * a1) % 14;
                CPr[a1] = f2accC(CPr[a1], Ezr, t);
                CPi[a1] = f2accC(CPi[a1], Ezi, t);
            }
            #pragma unroll
            for (int a1 = 1; a1 < 7; ++a1) {
                const int t = (k1 * a1) % 14;
                if (k1 == 1) { SQr[a1] = f2mul(Ozr, f2pk(S14f(t))); SQi[a1] = f2mul(Ozi, f2pk(S14f(t))); }
                else         { SQr[a1] = f2fma(Ozr, f2pk(S14f(t)), SQr[a1]); SQi[a1] = f2fma(Ozi, f2pk(S14f(t)), SQi[a1]); }
            }
        }

        // write z rows back (same column slots; thread-private)
        scol[0 * 8 * LANES] = make_ulonglong2(CPr[0], CPi[0]);
        scol[7 * 8 * LANES] = make_ulonglong2(CPr[7], CPi[7]);
        #pragma unroll
        for (int a1 = 1; a1 < 7; ++a1) {
            scol[a1        * 8 * LANES] = make_ulonglong2(f2sub(CPr[a1], SQi[a1]), f2add(CPi[a1], SQr[a1]));
            scol[(14 - a1) * 8 * LANES] = make_ulonglong2(f2add(CPr[a1], SQi[a1]), f2sub(CPi[a1], SQr[a1]));
        }
    }
    __syncthreads();

    // ------- stage 5: irfft along rows (k2 -> a2), folded, store -------
    float* ob = out + (size_t)b * 196 * 384 + ch;
    for (int a1 = h; a1 < 14; a1 += 4) {
        const ulonglong2* srow = S2 + a1 * 8 * LANES + lane;
        ull zr[8], zi[8];
        #pragma unroll
        for (int k = 0; k < 8; ++k) {
            const ulonglong2 v = srow[k * LANES];
            zr[k] = v.x; zi[k] = v.y;
        }
        const ull s1 = f2pk(1.0f / 196.0f);
        const ull s2 = f2pk(2.0f / 196.0f);
        zr[0] = f2mul(zr[0], s1);
        zr[7] = f2mul(zr[7], s1);
        #pragma unroll
        for (int k = 1; k < 7; ++k) { zr[k] = f2mul(zr[k], s2); zi[k] = f2mul(zi[k], s2); }

        const ull p = f2add(zr[0], zr[7]);
        const ull m = f2sub(zr[0], zr[7]);

        float* orow = ob + (size_t)a1 * 14 * 384;
        // a2 = 0
        {
            ull v = p;
            #pragma unroll
            for (int k = 1; k < 7; ++k) v = f2add(v, zr[k]);
            *(ull*)(orow + 0 * 384) = v;
        }
        // a2 = 7
        {
            ull v = m;
            #pragma unroll
            for (int k = 1; k < 7; ++k) v = (k & 1) ? f2sub(v, zr[k]) : f2add(v, zr[k]);
            *(ull*)(orow + 7 * 384) = v;
        }
        // pairs a2 / 14-a2
        #pragma unroll
        for (int a2 = 1; a2 < 7; ++a2) {
            ull E = (a2 & 1) ? m : p;
            ull Od;
            #pragma unroll
            for (int k = 1; k < 7; ++k) {
                const int t = (k * a2) % 14;
                E = f2fma(zr[k], f2pk(C14f(t)), E);
                if (k == 1) Od = f2mul(zi[1], f2pk(-S14f(t)));
                else        Od = f2fma(zi[k], f2pk(-S14f(t)), Od);
            }
            *(ull*)(orow + a2 * 384)        = f2add(E, Od);
            *(ull*)(orow + (14 - a2) * 384) = f2sub(E, Od);
        }
    }
}

extern "C" void kernel_launch(void* const* d_in, const int* in_sizes, int n_in,
                              void* d_out, int out_size)
{
    const float* x = (const float*)d_in[0];   // [512,196,384] f32
    const float* w = (const float*)d_in[1];   // [14,8,384,2]  f32
    float* out = (float*)d_out;               // [512,196,384] f32

    cudaFuncSetAttribute(gf_kernel, cudaFuncAttributeMaxDynamicSharedMemorySize, SMEM_BYTES);

    dim3 grid(512, 384 / CB);
    gf_kernel<<<grid, THREADS, SMEM_BYTES>>>(x, w, out);
}